// round 1
// baseline (speedup 1.0000x reference)
#include <cuda_runtime.h>

// Problem constants (fixed by setup_inputs)
#define BSZ 32
#define CIc 32
#define COc 32
#define NIc 8
#define NOc 8
#define PP  256   // 16x16 spatial
#define KKc 72    // NI*3*3

// Scratch (device globals: allocation-free per harness rules)
__device__ short g_votes[BSZ*COc*CIc*NOc*PP];   // [b][co][ci][no][p], value*256 (exact)
__device__ float g_logits[BSZ*CIc*COc*PP];      // [b][ci][co][p]
__device__ float g_smax[BSZ*CIc];
__device__ float g_ssum[BSZ*CIc];

__device__ __forceinline__ void ffma2(unsigned long long &acc, unsigned long long a, unsigned long long b) {
    asm("fma.rn.f32x2 %0, %1, %2, %0;" : "+l"(acc) : "l"(a), "l"(b));
}
__device__ __forceinline__ float lo32(unsigned long long v){ return __uint_as_float((unsigned)(v & 0xffffffffu)); }
__device__ __forceinline__ float hi32(unsigned long long v){ return __uint_as_float((unsigned)(v >> 32)); }

// ---------------------------------------------------------------------------
// Kernel 1: conv -> quantized votes (int16) + iteration-1 logits (exact ints)
// block = (b, ci), 256 threads (one per spatial position), 256 outputs each.
// ---------------------------------------------------------------------------
__global__ void __launch_bounds__(256, 2) conv_votes_kernel(
    const float* __restrict__ x, const float* __restrict__ w,
    const float* __restrict__ cb, const float* __restrict__ bias)
{
    extern __shared__ float sh[];
    float* ws  = sh;               // 18432 floats: weights [o][k], k contiguous
    float* xs  = sh + 18432;       // 2592 floats: padded x tile [8][18][18]
    float* cbs = xs + 2592;        // 256: conv bias
    int*   a1s = (int*)(cbs + 256);// 256: iter-1 activation (int, value*256)

    const int t   = threadIdx.x;
    const int blk = blockIdx.x;
    const int b   = blk >> 5, ci = blk & 31;

    // weights: [o][ni][ky][kx] is already k-contiguous per o
    {
        const float4* w4 = (const float4*)w;
        float4* d4 = (float4*)ws;
        #pragma unroll
        for (int i = 0; i < 18; i++) d4[t + i*256] = w4[t + i*256];
    }
    cbs[t] = cb[t];
    for (int i = t; i < 8*18*18; i += 256) xs[i] = 0.f;
    __syncthreads();
    {
        const float* xb = x + (b*CIc + ci)*NIc*PP;
        #pragma unroll
        for (int i = 0; i < 8; i++) {
            int idx = t + i*256;
            int ni = idx >> 8, rem = idx & 255;
            xs[ni*324 + ((rem>>4)+1)*18 + (rem&15) + 1] = xb[idx];
        }
    }
    // iteration-1 activation: route==0 -> preact = bias -> quant -> squash -> quant
    if (t < 32) {
        float pv[8]; float ss = 0.f;
        #pragma unroll
        for (int no = 0; no < 8; no++) {
            float q = rintf(__fmul_rn(bias[t*8+no], 256.f)) * 0.00390625f;
            pv[no] = q;
            ss = __fadd_rn(ss, __fmul_rn(q, q));
        }
        float n   = sqrtf(ss);
        float den = __fadd_rn(1.f, __fmul_rn(n, n));
        #pragma unroll
        for (int no = 0; no < 8; no++) {
            float a = __fdiv_rn(__fmul_rn(pv[no], n), den);
            a1s[t*8+no] = __float2int_rn(__fmul_rn(a, 256.f));
        }
    }
    __syncthreads();

    const int y = t >> 4, xc = t & 15;
    // Gather 72-value window, packed as f32x2 pairs for FFMA2
    unsigned long long xp[36];
    {
        float tmp[72];
        #pragma unroll
        for (int ni = 0; ni < 8; ni++)
            #pragma unroll
            for (int ky = 0; ky < 3; ky++)
                #pragma unroll
                for (int kx = 0; kx < 3; kx++)
                    tmp[ni*9 + ky*3 + kx] = xs[ni*324 + (y+ky)*18 + xc + kx];
        #pragma unroll
        for (int j = 0; j < 36; j++)
            xp[j] = (unsigned long long)__float_as_uint(tmp[2*j]) |
                    ((unsigned long long)__float_as_uint(tmp[2*j+1]) << 32);
    }

    short* vptr = g_votes + ((b*32)*32 + ci)*2048 + t;    // + co*65536 + no*256
    float* lptr = g_logits + ((b*32 + ci)*32)*256 + t;    // + co*256
    int dsum = 0;
    for (int o = 0; o < 256; o++) {
        const ulonglong2* wo = (const ulonglong2*)(ws + o*72);
        unsigned long long acc0 = 0ull, acc1 = 0ull;
        #pragma unroll
        for (int j = 0; j < 18; j++) {
            ulonglong2 ww = wo[j];          // 4 weights, broadcast LDS.128
            ffma2(acc0, ww.x, xp[2*j]);
            ffma2(acc1, ww.y, xp[2*j+1]);
        }
        float vsum = ((lo32(acc0)+hi32(acc0)) + (lo32(acc1)+hi32(acc1))) + cbs[o];
        int vi = __float2int_rn(vsum * 256.f);   // quant(votes), round half-even
        int co = o >> 3, no = o & 7;
        vptr[co*65536 + no*256] = (short)vi;
        dsum += a1s[o] * vi;                     // iter-1 distances (exact int)
        if (no == 7) {
            // logits1 = rint(dsum/256)/256, exact in fp32 (|dsum| << 2^24)
            lptr[co*256] = rintf((float)dsum * 0.00390625f) * 0.00390625f;
            dsum = 0;
        }
    }
}

// ---------------------------------------------------------------------------
// Kernel 2: softmax stats per (b, ci) over 8192 logits
// ---------------------------------------------------------------------------
__global__ void __launch_bounds__(256) softmax_kernel()
{
    const int row = blockIdx.x;            // b*32 + ci
    const float* lp = g_logits + row*8192;
    const int t = threadIdx.x;
    float fl[32];
    #pragma unroll
    for (int i = 0; i < 32; i++) fl[i] = lp[i*256 + t];
    float m = fl[0];
    #pragma unroll
    for (int i = 1; i < 32; i++) m = fmaxf(m, fl[i]);
    __shared__ float red[8];
    #pragma unroll
    for (int off = 16; off; off >>= 1) m = fmaxf(m, __shfl_xor_sync(0xffffffffu, m, off));
    if ((t & 31) == 0) red[t >> 5] = m;
    __syncthreads();
    float M = red[0];
    #pragma unroll
    for (int i = 1; i < 8; i++) M = fmaxf(M, red[i]);
    __syncthreads();
    float s = 0.f;
    #pragma unroll
    for (int i = 0; i < 32; i++) s += expf(fl[i] - M);
    #pragma unroll
    for (int off = 16; off; off >>= 1) s += __shfl_xor_sync(0xffffffffu, s, off);
    if ((t & 31) == 0) red[t >> 5] = s;
    __syncthreads();
    if (t == 0) {
        float S = red[0];
        for (int i = 1; i < 8; i++) S += red[i];
        g_smax[row] = M;
        g_ssum[row] = S;
    }
}

// ---------------------------------------------------------------------------
// Kernel 3: fused routing iteration. block = (b, co); votes tile staged in SMEM.
//   pass1: route (softmax+quant) -> preactivate (exact int) -> squash -> activation
//   pass2: agreement distances -> logits update (skipped on last iteration)
// ---------------------------------------------------------------------------
__global__ void __launch_bounds__(256) route_kernel(
    const float* __restrict__ bias, float* __restrict__ out, int last)
{
    extern __shared__ char shb[];
    short* sv    = (short*)shb;                 // 65536 shorts = 128 KB
    float* smaxs = (float*)(shb + 131072);      // 32
    float* ssums = smaxs + 32;                  // 32
    float* sb    = ssums + 32;                  // 8

    const int t   = threadIdx.x;
    const int blk = blockIdx.x;                 // b*32 + co
    const int b   = blk >> 5, co = blk & 31;

    {
        const uint4* src = (const uint4*)(g_votes + blk*65536);
        uint4* dst = (uint4*)sv;
        #pragma unroll
        for (int i = 0; i < 32; i++) dst[t + i*256] = src[t + i*256];
    }
    if (t < 32) { smaxs[t] = g_smax[b*32 + t]; ssums[t] = g_ssum[b*32 + t]; }
    if (t < 8)  sb[t] = bias[co*8 + t];
    __syncthreads();

    float l[32];
    int S[8] = {0,0,0,0,0,0,0,0};
    const float* lgp = g_logits + (b*32)*8192 + co*256 + t;
    #pragma unroll
    for (int c = 0; c < 32; c++) {
        float lv = lgp[c*8192];
        l[c] = lv;
        float e = expf(lv - smaxs[c]);
        int r = __float2int_rn(__fmul_rn(__fdiv_rn(e, ssums[c]), 256.f)); // quant(route)*256
        if (r) {
            #pragma unroll
            for (int no = 0; no < 8; no++)
                S[no] += r * (int)sv[(c*8 + no)*256 + t];
        }
    }
    float pq[8]; float ss = 0.f;
    #pragma unroll
    for (int no = 0; no < 8; no++) {
        // preactivate = S/65536 + bias (S/65536 exact), then quant
        float pre = __fadd_rn(__fmul_rn((float)S[no], 1.52587890625e-05f), sb[no]);
        float q = rintf(__fmul_rn(pre, 256.f)) * 0.00390625f;
        pq[no] = q;
        ss = __fadd_rn(ss, __fmul_rn(q, q));
    }
    float n   = sqrtf(ss);
    float den = __fadd_rn(1.f, __fmul_rn(n, n));
    int ai[8];
    #pragma unroll
    for (int no = 0; no < 8; no++) {
        float a = __fdiv_rn(__fmul_rn(pq[no], n), den);   // squash
        int q = __float2int_rn(__fmul_rn(a, 256.f));      // quant(activation)*256
        ai[no] = q;
        out[(blk*8 + no)*256 + t] = (float)q * 0.00390625f;
    }
    if (!last) {
        float* lw = g_logits + (b*32)*8192 + co*256 + t;
        #pragma unroll
        for (int c = 0; c < 32; c++) {
            int m = 0;
            #pragma unroll
            for (int no = 0; no < 8; no++)
                m += ai[no] * (int)sv[(c*8 + no)*256 + t];   // distances (exact int)
            float lg = __fadd_rn(l[c], __fmul_rn((float)m, 1.52587890625e-05f)); // exact
            lw[c*8192] = rintf(__fmul_rn(lg, 256.f)) * 0.00390625f;
        }
    }
}

// ---------------------------------------------------------------------------
extern "C" void kernel_launch(void* const* d_in, const int* in_sizes, int n_in,
                              void* d_out, int out_size)
{
    const float* x    = (const float*)d_in[0];
    const float* w    = (const float*)d_in[1];
    const float* cb   = (const float*)d_in[2];
    const float* bias = (const float*)d_in[3];
    float* out = (float*)d_out;
    (void)in_sizes; (void)n_in; (void)out_size;

    const int CONV_SMEM  = (18432 + 2592 + 256)*4 + 256*4;   // 86144 B
    const int ROUTE_SMEM = 131072 + (32 + 32 + 8)*4;          // 131360 B
    cudaFuncSetAttribute(conv_votes_kernel, cudaFuncAttributeMaxDynamicSharedMemorySize, CONV_SMEM);
    cudaFuncSetAttribute(route_kernel,      cudaFuncAttributeMaxDynamicSharedMemorySize, ROUTE_SMEM);

    conv_votes_kernel<<<1024, 256, CONV_SMEM>>>(x, w, cb, bias);  // + iteration 1 (folded)
    softmax_kernel<<<1024, 256>>>();                              // iteration 2
    route_kernel<<<1024, 256, ROUTE_SMEM>>>(bias, out, 0);
    softmax_kernel<<<1024, 256>>>();                              // iteration 3
    route_kernel<<<1024, 256, ROUTE_SMEM>>>(bias, out, 1);
}

// round 2
// speedup vs baseline: 1.7405x; 1.7405x over previous
#include <cuda_runtime.h>

// Problem constants (fixed by setup_inputs)
#define BSZ 32
#define CIc 32
#define COc 32
#define NIc 8
#define NOc 8
#define PP  256   // 16x16 spatial
#define KKc 72    // NI*3*3

// Scratch (device globals: allocation-free per harness rules)
__device__ short g_votes[BSZ*COc*CIc*NOc*PP];   // [b][co][ci][no][p], value*256 (exact)
__device__ float g_logits[BSZ*CIc*COc*PP];      // [b][ci][co][p]
__device__ float g_smax[BSZ*CIc];
__device__ float g_ssum[BSZ*CIc];

__device__ __forceinline__ void ffma2(unsigned long long &acc, unsigned long long a, unsigned long long b) {
    asm("fma.rn.f32x2 %0, %1, %2, %0;" : "+l"(acc) : "l"(a), "l"(b));
}
__device__ __forceinline__ float lo32(unsigned long long v){ return __uint_as_float((unsigned)(v & 0xffffffffu)); }
__device__ __forceinline__ float hi32(unsigned long long v){ return __uint_as_float((unsigned)(v >> 32)); }

// ---------------------------------------------------------------------------
// Kernel 1: conv -> quantized votes (int16) + iteration-1 logits (exact ints)
// block = (b, ci). Register-tiled GEMM: D[p=256, o=256] = X[p,72] * W[72,o].
// Thread tile 4p x 8o, FFMA2 pairs along k. smem: W^T [k2][o], im2col X [k2][p].
// ---------------------------------------------------------------------------
__global__ void __launch_bounds__(256) conv_votes_kernel(
    const float* __restrict__ x, const float* __restrict__ w,
    const float* __restrict__ cb, const float* __restrict__ bias)
{
    extern __shared__ char sh[];
    float2* w2  = (float2*)sh;                   // [36][256] float2 = 73728 B
    float2* xim = (float2*)(sh + 73728);         // [36][256] float2 = 73728 B
    float*  xp  = (float*)(sh + 147456);         // padded tile 8*18*18 = 10368 B
    float*  cbs = (float*)(sh + 157824);         // 256 floats
    int*    a1s = (int*)(sh + 158848);           // 256 ints

    const int t  = threadIdx.x;
    const int b  = blockIdx.x >> 5, ci = blockIdx.x & 31;

    // --- weight transpose: w2[k2][o] = (w[o][2k2], w[o][2k2+1]) ---
    {
        const float2* wg = (const float2*)(w + t*KKc);   // this thread's o = t
        #pragma unroll
        for (int i = 0; i < 36; i++) w2[i*256 + t] = wg[i];   // conflict-free STS
    }
    cbs[t] = cb[t];
    for (int i = t; i < 8*18*18; i += 256) xp[i] = 0.f;
    __syncthreads();
    {
        const float* xb = x + (b*CIc + ci)*NIc*PP;
        #pragma unroll
        for (int i = 0; i < 8; i++) {
            int idx = t + i*256;
            int ni = idx >> 8, rem = idx & 255;
            xp[ni*324 + ((rem>>4)+1)*18 + (rem&15) + 1] = xb[idx];
        }
    }
    __syncthreads();

    // --- im2col into xim[k2][p] (p = t) ---
    {
        const int y = t >> 4, xc = t & 15;
        #pragma unroll
        for (int k2 = 0; k2 < 36; k2++) {
            const int k0 = 2*k2, k1 = k0 + 1;
            const int ni0 = k0/9, r0 = k0%9, ky0 = r0/3, kx0 = r0%3;
            const int ni1 = k1/9, r1 = k1%9, ky1 = r1/3, kx1 = r1%3;
            float a  = xp[ni0*324 + (y+ky0)*18 + xc + kx0];
            float bb = xp[ni1*324 + (y+ky1)*18 + xc + kx1];
            xim[k2*256 + t] = make_float2(a, bb);
        }
    }

    // iteration-1 activation: route==0 -> preact = bias -> quant -> squash -> quant
    if (t < 32) {
        float pv[8]; float ss = 0.f;
        #pragma unroll
        for (int no = 0; no < 8; no++) {
            float q = rintf(__fmul_rn(bias[t*8+no], 256.f)) * 0.00390625f;
            pv[no] = q;
            ss = __fadd_rn(ss, __fmul_rn(q, q));
        }
        float n   = sqrtf(ss);
        float den = __fadd_rn(1.f, __fmul_rn(n, n));
        #pragma unroll
        for (int no = 0; no < 8; no++) {
            float a = __fdiv_rn(__fmul_rn(pv[no], n), den);
            a1s[t*8+no] = __float2int_rn(__fmul_rn(a, 256.f));
        }
    }
    __syncthreads();

    const int lane = t & 31;
    const int warp = t >> 5;
    short* vbase = g_votes + ((b*32)*32 + ci)*2048;   // + co*65536 + no*256 + p
    float* lbase = g_logits + ((b*32 + ci)*32)*256;   // + co*256 + p

    #pragma unroll 1
    for (int ppass = 0; ppass < 2; ppass++) {
        const int pbase = ppass*128 + lane;
        #pragma unroll 1
        for (int opass = 0; opass < 4; opass++) {
            const int obase = warp*32 + opass*8;
            unsigned long long acc[4][8] = {};
            #pragma unroll 12
            for (int k2 = 0; k2 < 36; k2++) {
                const float2* xrow = xim + k2*256;
                unsigned long long xv[4];
                #pragma unroll
                for (int i = 0; i < 4; i++)
                    xv[i] = *(const unsigned long long*)&xrow[pbase + 32*i];
                const ulonglong2* wrow = (const ulonglong2*)(w2 + k2*256 + obase);
                #pragma unroll
                for (int j = 0; j < 4; j++) {
                    ulonglong2 wv = wrow[j];   // broadcast LDS.128: 2 outputs' k-pairs
                    #pragma unroll
                    for (int i = 0; i < 4; i++) {
                        ffma2(acc[i][2*j],   xv[i], wv.x);
                        ffma2(acc[i][2*j+1], xv[i], wv.y);
                    }
                }
            }
            const int co = obase >> 3;    // obase is a multiple of 8
            #pragma unroll
            for (int i = 0; i < 4; i++) {
                const int p = pbase + 32*i;
                int dsum = 0;
                #pragma unroll
                for (int no = 0; no < 8; no++) {
                    const int o = obase + no;
                    float v = __fadd_rn(__fadd_rn(lo32(acc[i][no]), hi32(acc[i][no])), cbs[o]);
                    int vi = __float2int_rn(v * 256.f);   // quant(votes), half-even
                    vbase[co*65536 + no*256 + p] = (short)vi;
                    dsum += a1s[o] * vi;                  // iter-1 distances (exact int)
                }
                // logits1 = rint(dsum/256)/256, exact in fp32 (|dsum| << 2^24)
                lbase[co*256 + p] = rintf((float)dsum * 0.00390625f) * 0.00390625f;
            }
        }
    }
}

// ---------------------------------------------------------------------------
// Kernel 2: softmax stats per (b, ci) over 8192 logits
// ---------------------------------------------------------------------------
__global__ void __launch_bounds__(256) softmax_kernel()
{
    const int row = blockIdx.x;            // b*32 + ci
    const float* lp = g_logits + row*8192;
    const int t = threadIdx.x;
    float fl[32];
    #pragma unroll
    for (int i = 0; i < 32; i++) fl[i] = lp[i*256 + t];
    float m = fl[0];
    #pragma unroll
    for (int i = 1; i < 32; i++) m = fmaxf(m, fl[i]);
    __shared__ float red[8];
    #pragma unroll
    for (int off = 16; off; off >>= 1) m = fmaxf(m, __shfl_xor_sync(0xffffffffu, m, off));
    if ((t & 31) == 0) red[t >> 5] = m;
    __syncthreads();
    float M = red[0];
    #pragma unroll
    for (int i = 1; i < 8; i++) M = fmaxf(M, red[i]);
    __syncthreads();
    float s = 0.f;
    #pragma unroll
    for (int i = 0; i < 32; i++) s += expf(fl[i] - M);
    #pragma unroll
    for (int off = 16; off; off >>= 1) s += __shfl_xor_sync(0xffffffffu, s, off);
    if ((t & 31) == 0) red[t >> 5] = s;
    __syncthreads();
    if (t == 0) {
        float S = red[0];
        for (int i = 1; i < 8; i++) S += red[i];
        g_smax[row] = M;
        g_ssum[row] = S;
    }
}

// ---------------------------------------------------------------------------
// Kernel 3: fused routing iteration. block = (b, co, p-half); 128 threads.
// 64KB vote tile staged in SMEM -> 3 blocks/SM (overlap staging with compute).
//   pass1: route (softmax+quant) -> preactivate (exact int) -> squash -> activation
//   pass2: agreement distances -> logits update (skipped on last iteration)
// ---------------------------------------------------------------------------
__global__ void __launch_bounds__(128) route_kernel(
    const float* __restrict__ bias, float* __restrict__ out, int last)
{
    extern __shared__ char shb[];
    short* sv    = (short*)shb;                 // [32ci][8no][128p] = 65536 B
    float* smaxs = (float*)(shb + 65536);       // 32
    float* ssums = (float*)(shb + 65664);       // 32
    float* sb    = (float*)(shb + 65792);       // 8

    const int t   = threadIdx.x;                // p index within half
    const int blk = blockIdx.x;                 // (b*32+co)*2 + ph
    const int bco = blk >> 1, ph = blk & 1;
    const int b   = bco >> 5, co = bco & 31;

    {
        const short* src0 = g_votes + bco*65536 + ph*128;
        uint4* dst = (uint4*)sv;
        #pragma unroll
        for (int r = 0; r < 32; r++) {
            int idx = r*128 + t;           // 0..4095 uint4
            int cino = idx >> 4, ch = idx & 15;
            dst[idx] = *(const uint4*)(src0 + cino*256 + ch*8);
        }
    }
    if (t < 32) { smaxs[t] = g_smax[b*32 + t]; ssums[t] = g_ssum[b*32 + t]; }
    if (t < 8)  sb[t] = bias[co*8 + t];
    __syncthreads();

    float l[32];
    int S[8] = {0,0,0,0,0,0,0,0};
    const float* lgp = g_logits + (b*32)*8192 + co*256 + ph*128 + t;
    #pragma unroll
    for (int c = 0; c < 32; c++) {
        float lv = lgp[c*8192];
        l[c] = lv;
        float e = expf(lv - smaxs[c]);
        int r = __float2int_rn(__fmul_rn(__fdiv_rn(e, ssums[c]), 256.f)); // quant(route)*256
        if (r) {
            #pragma unroll
            for (int no = 0; no < 8; no++)
                S[no] += r * (int)sv[(c*8 + no)*128 + t];
        }
    }
    float pq[8]; float ss = 0.f;
    #pragma unroll
    for (int no = 0; no < 8; no++) {
        // preactivate = S/65536 + bias (S/65536 exact), then quant
        float pre = __fadd_rn(__fmul_rn((float)S[no], 1.52587890625e-05f), sb[no]);
        float q = rintf(__fmul_rn(pre, 256.f)) * 0.00390625f;
        pq[no] = q;
        ss = __fadd_rn(ss, __fmul_rn(q, q));
    }
    float n   = sqrtf(ss);
    float den = __fadd_rn(1.f, __fmul_rn(n, n));
    int ai[8];
    #pragma unroll
    for (int no = 0; no < 8; no++) {
        float a = __fdiv_rn(__fmul_rn(pq[no], n), den);   // squash
        int q = __float2int_rn(__fmul_rn(a, 256.f));      // quant(activation)*256
        ai[no] = q;
        out[(bco*8 + no)*256 + ph*128 + t] = (float)q * 0.00390625f;
    }
    if (!last) {
        float* lw = g_logits + (b*32)*8192 + co*256 + ph*128 + t;
        #pragma unroll
        for (int c = 0; c < 32; c++) {
            int m = 0;
            #pragma unroll
            for (int no = 0; no < 8; no++)
                m += ai[no] * (int)sv[(c*8 + no)*128 + t];   // distances (exact int)
            float lg = __fadd_rn(l[c], __fmul_rn((float)m, 1.52587890625e-05f)); // exact
            lw[c*8192] = rintf(__fmul_rn(lg, 256.f)) * 0.00390625f;
        }
    }
}

// ---------------------------------------------------------------------------
extern "C" void kernel_launch(void* const* d_in, const int* in_sizes, int n_in,
                              void* d_out, int out_size)
{
    const float* x    = (const float*)d_in[0];
    const float* w    = (const float*)d_in[1];
    const float* cb   = (const float*)d_in[2];
    const float* bias = (const float*)d_in[3];
    float* out = (float*)d_out;
    (void)in_sizes; (void)n_in; (void)out_size;

    const int CONV_SMEM  = 159872;
    const int ROUTE_SMEM = 65824;
    cudaFuncSetAttribute(conv_votes_kernel, cudaFuncAttributeMaxDynamicSharedMemorySize, CONV_SMEM);
    cudaFuncSetAttribute(route_kernel,      cudaFuncAttributeMaxDynamicSharedMemorySize, ROUTE_SMEM);

    conv_votes_kernel<<<1024, 256, CONV_SMEM>>>(x, w, cb, bias);  // + iteration 1 (folded)
    softmax_kernel<<<1024, 256>>>();                              // iteration 2
    route_kernel<<<2048, 128, ROUTE_SMEM>>>(bias, out, 0);
    softmax_kernel<<<1024, 256>>>();                              // iteration 3
    route_kernel<<<2048, 128, ROUTE_SMEM>>>(bias, out, 1);
}